// round 7
// baseline (speedup 1.0000x reference)
#include <cuda_runtime.h>
#include <math.h>

#define N_NODES 50000
#define HC 128
#define NHEAD 2
#define CDIM 64
#define E_EDGES 800000
#define ETOT (E_EDGES + N_NODES)
#define NEG_SLOPE 0.2f
#define EPS_GN 1e-5f

// ---------------- scratch (static device globals; no allocations) ------------
__device__ float d_xl[N_NODES * HC];
__device__ float d_xr[N_NODES * HC];
__device__ float d_feat[N_NODES * HC];
__device__ float d_acc[N_NODES * HC];
__device__ float d_e[ETOT * NHEAD];
__device__ float d_emax[N_NODES * NHEAD];
__device__ float d_denom[N_NODES * NHEAD];
__device__ float d_sum[HC];
__device__ float d_sumsq[HC];

// ---------------- GEMM: Y[N x 128] = X[N x 128] @ W[128 x 128] + b ----------
// 256 threads, 64 rows/block, full 128-col tile, K chunked by 32.
__global__ __launch_bounds__(256) void gemm128(
    const float* __restrict__ X, const float* __restrict__ W,
    const float* __restrict__ bias, float* __restrict__ Y)
{
    __shared__ float Xs[64][32];
    __shared__ float Ws[32][128];

    const int tid = threadIdx.x;
    const int tx = tid & 31;        // column group: cols tx*4 .. tx*4+3
    const int ty = tid >> 5;        // row group:    rows ty*8 .. ty*8+7
    const int r0 = blockIdx.x * 64;

    float acc[8][4];
#pragma unroll
    for (int i = 0; i < 8; i++)
#pragma unroll
        for (int j = 0; j < 4; j++) acc[i][j] = 0.f;

    for (int kc = 0; kc < 128; kc += 32) {
        // load W chunk: 32x128 floats = 1024 float4, 4 per thread
#pragma unroll
        for (int i = 0; i < 4; i++) {
            int f = i * 256 + tid;          // float4 index
            int row = f >> 5, c4 = f & 31;
            *(float4*)&Ws[row][c4 * 4] =
                *(const float4*)&W[(kc + row) * 128 + c4 * 4];
        }
        // load X chunk: 64x32 floats = 512 float4, 2 per thread
#pragma unroll
        for (int i = 0; i < 2; i++) {
            int f = i * 256 + tid;
            int rr = f >> 3, c4 = f & 7;
            int gr = r0 + rr;
            float4 v = make_float4(0.f, 0.f, 0.f, 0.f);
            if (gr < N_NODES)
                v = *(const float4*)&X[gr * 128 + kc + c4 * 4];
            *(float4*)&Xs[rr][c4 * 4] = v;
        }
        __syncthreads();

#pragma unroll
        for (int kk = 0; kk < 32; kk++) {
            float4 w = *(const float4*)&Ws[kk][tx * 4];
#pragma unroll
            for (int i = 0; i < 8; i++) {
                float a = Xs[ty * 8 + i][kk];
                acc[i][0] += a * w.x;
                acc[i][1] += a * w.y;
                acc[i][2] += a * w.z;
                acc[i][3] += a * w.w;
            }
        }
        __syncthreads();
    }

    float4 bv = *(const float4*)&bias[tx * 4];
#pragma unroll
    for (int i = 0; i < 8; i++) {
        int row = r0 + ty * 8 + i;
        if (row < N_NODES) {
            float4 o;
            o.x = acc[i][0] + bv.x;
            o.y = acc[i][1] + bv.y;
            o.z = acc[i][2] + bv.z;
            o.w = acc[i][3] + bv.w;
            *(float4*)&Y[row * 128 + tx * 4] = o;
        }
    }
}

// ---------------- per-layer init: acc=bias, emax=-inf, denom=1e-16 ----------
__global__ void init_layer(const float* __restrict__ bias)
{
    int idx = blockIdx.x * blockDim.x + threadIdx.x;
    if (idx < N_NODES * HC) d_acc[idx] = bias[idx & 127];
    if (idx < N_NODES * NHEAD) {
        d_emax[idx] = -INFINITY;
        d_denom[idx] = 1e-16f;
    }
    if (idx < HC) { d_sum[idx] = 0.f; d_sumsq[idx] = 0.f; }
}

// ---------------- edge pass A: attention scores + segment max ---------------
// one warp per edge.  edge_index arrives as int32 (harness converts int64).
__global__ __launch_bounds__(256) void edge_scores(
    const int* __restrict__ ei, const float* __restrict__ att)
{
    int widx = (blockIdx.x * blockDim.x + threadIdx.x) >> 5;
    int lane = threadIdx.x & 31;
    if (widx >= ETOT) return;

    int s, d;
    if (widx < E_EDGES) {
        s = ei[widx];
        d = ei[E_EDGES + widx];
    } else {
        s = d = widx - E_EDGES;
    }
    int ch = lane * 4;
    float4 a = *(const float4*)&d_xl[(long)s * HC + ch];
    float4 b = *(const float4*)&d_xr[(long)d * HC + ch];
    float4 av = *(const float4*)&att[ch];

    float m, p = 0.f;
    m = a.x + b.x; m = (m > 0.f) ? m : NEG_SLOPE * m; p += m * av.x;
    m = a.y + b.y; m = (m > 0.f) ? m : NEG_SLOPE * m; p += m * av.y;
    m = a.z + b.z; m = (m > 0.f) ? m : NEG_SLOPE * m; p += m * av.z;
    m = a.w + b.w; m = (m > 0.f) ? m : NEG_SLOPE * m; p += m * av.w;

    // reduce within each 16-lane half (head 0: lanes 0-15, head 1: 16-31)
    p += __shfl_down_sync(0xffffffffu, p, 8, 16);
    p += __shfl_down_sync(0xffffffffu, p, 4, 16);
    p += __shfl_down_sync(0xffffffffu, p, 2, 16);
    p += __shfl_down_sync(0xffffffffu, p, 1, 16);

    if ((lane & 15) == 0) {
        int h = lane >> 4;
        d_e[widx * NHEAD + h] = p;
        float* addr = &d_emax[d * NHEAD + h];
        if (p >= 0.f) atomicMax((int*)addr, __float_as_int(p));
        else          atomicMin((unsigned int*)addr, __float_as_uint(p));
    }
}

// ---------------- edge pass B: exp + segment sum ----------------------------
__global__ void edge_exp(const int* __restrict__ ei)
{
    int idx = blockIdx.x * blockDim.x + threadIdx.x;
    if (idx >= ETOT * NHEAD) return;
    int e = idx >> 1;
    int h = idx & 1;
    int d = (e < E_EDGES) ? ei[E_EDGES + e] : (e - E_EDGES);
    float v = expf(d_e[idx] - d_emax[d * NHEAD + h]);
    d_e[idx] = v;
    atomicAdd(&d_denom[d * NHEAD + h], v);
}

// ---------------- edge pass C: weighted aggregation -------------------------
// one warp per edge
__global__ __launch_bounds__(256) void edge_agg(const int* __restrict__ ei)
{
    int widx = (blockIdx.x * blockDim.x + threadIdx.x) >> 5;
    int lane = threadIdx.x & 31;
    if (widx >= ETOT) return;

    int s, d;
    if (widx < E_EDGES) {
        s = ei[widx];
        d = ei[E_EDGES + widx];
    } else {
        s = d = widx - E_EDGES;
    }
    int h = lane >> 4;
    float a = 0.f;
    if ((lane & 15) == 0)
        a = d_e[widx * NHEAD + h] / d_denom[d * NHEAD + h];
    float alpha = __shfl_sync(0xffffffffu, a, lane & 16);

    float4 x = *(const float4*)&d_xl[(long)s * HC + lane * 4];
    float* o = &d_acc[(long)d * HC + lane * 4];
    atomicAdd(o + 0, x.x * alpha);
    atomicAdd(o + 1, x.y * alpha);
    atomicAdd(o + 2, x.z * alpha);
    atomicAdd(o + 3, x.w * alpha);
}

// ---------------- GraphNorm: column sum ------------------------------------
__global__ void colsum()
{
    int c = threadIdx.x;  // 128 threads
    float s = 0.f;
    for (int r = blockIdx.x; r < N_NODES; r += gridDim.x)
        s += d_acc[r * HC + c];
    atomicAdd(&d_sum[c], s);
}

__global__ void colsumsq(const float* __restrict__ ms)
{
    int c = threadIdx.x;
    float shift = ms[c] * (d_sum[c] * (1.f / N_NODES));
    float s = 0.f;
    for (int r = blockIdx.x; r < N_NODES; r += gridDim.x) {
        float t = d_acc[r * HC + c] - shift;
        s += t * t;
    }
    atomicAdd(&d_sumsq[c], s);
}

__global__ void norm_relu(const float* __restrict__ g,
                          const float* __restrict__ be,
                          const float* __restrict__ ms)
{
    int idx = blockIdx.x * blockDim.x + threadIdx.x;
    if (idx >= N_NODES * HC) return;
    int c = idx & 127;
    float mean = d_sum[c] * (1.f / N_NODES);
    float t = d_acc[idx] - ms[c] * mean;
    float inv = rsqrtf(d_sumsq[c] * (1.f / N_NODES) + EPS_GN);
    float y = g[c] * t * inv + be[c];
    d_feat[idx] = (y > 0.f) ? y : 0.f;
}

// ---------------- fused MLP head: relu(feat@W1+b1)@W2+b2 --------------------
// one warp per node; W1 (128x64) staged in smem
__global__ __launch_bounds__(256) void mlp_head(
    const float* __restrict__ W1, const float* __restrict__ b1,
    const float* __restrict__ W2, const float* __restrict__ b2,
    float* __restrict__ out)
{
    __shared__ float W1s[128 * 64];
    __shared__ float W2s[128];
    __shared__ float b1s[64];
    __shared__ float xs[8][128];

    int tid = threadIdx.x;
    for (int i = tid; i < 128 * 64; i += 256) W1s[i] = W1[i];
    if (tid < 128) W2s[tid] = W2[tid];
    if (tid < 64) b1s[tid] = b1[tid];
    __syncthreads();

    int w = tid >> 5, lane = tid & 31;
    float bb0 = b2[0], bb1 = b2[1];

    for (int n = blockIdx.x * 8 + w; n < N_NODES; n += gridDim.x * 8) {
        *(float4*)&xs[w][lane * 4] =
            *(const float4*)&d_feat[(long)n * HC + lane * 4];
        __syncwarp();

        float h0 = b1s[lane], h1 = b1s[lane + 32];
#pragma unroll
        for (int k = 0; k < 128; k++) {
            float x = xs[w][k];
            h0 += x * W1s[k * 64 + lane];
            h1 += x * W1s[k * 64 + lane + 32];
        }
        h0 = (h0 > 0.f) ? h0 : 0.f;
        h1 = (h1 > 0.f) ? h1 : 0.f;

        float p0 = h0 * W2s[lane * 2]     + h1 * W2s[(lane + 32) * 2];
        float p1 = h0 * W2s[lane * 2 + 1] + h1 * W2s[(lane + 32) * 2 + 1];
#pragma unroll
        for (int off = 16; off > 0; off >>= 1) {
            p0 += __shfl_down_sync(0xffffffffu, p0, off);
            p1 += __shfl_down_sync(0xffffffffu, p1, off);
        }
        if (lane == 0) {
            out[n * 2]     = p0 + bb0;
            out[n * 2 + 1] = p1 + bb1;
        }
        __syncwarp();
    }
}

// ---------------- driver -----------------------------------------------------
extern "C" void kernel_launch(void* const* d_in, const int* in_sizes, int n_in,
                              void* d_out, int out_size)
{
    const float* x      = (const float*)d_in[0];
    const int*   ei     = (const int*)d_in[1];      // int64 -> int32 by harness
    const float* Wl0 = (const float*)d_in[2];
    const float* bl0 = (const float*)d_in[3];
    const float* Wr0 = (const float*)d_in[4];
    const float* br0 = (const float*)d_in[5];
    const float* att0  = (const float*)d_in[6];
    const float* bias0 = (const float*)d_in[7];
    const float* Wl1 = (const float*)d_in[8];
    const float* bl1 = (const float*)d_in[9];
    const float* Wr1 = (const float*)d_in[10];
    const float* br1 = (const float*)d_in[11];
    const float* att1  = (const float*)d_in[12];
    const float* bias1 = (const float*)d_in[13];
    const float* g0  = (const float*)d_in[14];
    const float* be0 = (const float*)d_in[15];
    const float* ms0 = (const float*)d_in[16];
    const float* g1  = (const float*)d_in[17];
    const float* be1 = (const float*)d_in[18];
    const float* ms1 = (const float*)d_in[19];
    const float* W1 = (const float*)d_in[20];
    const float* b1 = (const float*)d_in[21];
    const float* W2 = (const float*)d_in[22];
    const float* b2 = (const float*)d_in[23];
    float* out = (float*)d_out;

    float *p_xl, *p_xr, *p_feat;
    cudaGetSymbolAddress((void**)&p_xl,   d_xl);
    cudaGetSymbolAddress((void**)&p_xr,   d_xr);
    cudaGetSymbolAddress((void**)&p_feat, d_feat);

    const int gemm_grid  = (N_NODES + 63) / 64;                 // 782
    const int init_grid  = (N_NODES * HC + 255) / 256;          // 25000
    const int edge_grid  = (ETOT * 32 + 255) / 256;             // warp/edge
    const int exp_grid   = (ETOT * NHEAD + 255) / 256;
    const int red_grid   = 512;

    // ---------- layer 0 ----------
    gemm128<<<gemm_grid, 256>>>(x, Wl0, bl0, p_xl);
    gemm128<<<gemm_grid, 256>>>(x, Wr0, br0, p_xr);
    init_layer<<<init_grid, 256>>>(bias0);
    edge_scores<<<edge_grid, 256>>>(ei, att0);
    edge_exp<<<exp_grid, 256>>>(ei);
    edge_agg<<<edge_grid, 256>>>(ei);
    colsum<<<red_grid, 128>>>();
    colsumsq<<<red_grid, 128>>>(ms0);
    norm_relu<<<init_grid, 256>>>(g0, be0, ms0);

    // ---------- layer 1 ----------
    gemm128<<<gemm_grid, 256>>>(p_feat, Wl1, bl1, p_xl);
    gemm128<<<gemm_grid, 256>>>(p_feat, Wr1, br1, p_xr);
    init_layer<<<init_grid, 256>>>(bias1);
    edge_scores<<<edge_grid, 256>>>(ei, att1);
    edge_exp<<<exp_grid, 256>>>(ei);
    edge_agg<<<edge_grid, 256>>>(ei);
    colsum<<<red_grid, 128>>>();
    colsumsq<<<red_grid, 128>>>(ms1);
    norm_relu<<<init_grid, 256>>>(g1, be1, ms1);

    // ---------- MLP head ----------
    mlp_head<<<(N_NODES + 7) / 8, 256>>>(W1, b1, W2, b2, out);
}

// round 9
// speedup vs baseline: 1.8482x; 1.8482x over previous
#include <cuda_runtime.h>
#include <math.h>

#define N_NODES 50000
#define HC 128
#define NHEAD 2
#define CDIM 64
#define E_EDGES 800000
#define ETOT (E_EDGES + N_NODES)
#define NEG_SLOPE 0.2f
#define EPS_GN 1e-5f

// ---------------- scratch (static device globals; no allocations) ------------
__device__ float d_xl[N_NODES * HC];
__device__ float d_xr[N_NODES * HC];
__device__ float d_feat[N_NODES * HC];
__device__ float d_acc[N_NODES * HC];
__device__ float d_e[ETOT * NHEAD];
__device__ float d_sum[HC];
__device__ float d_sumsq[HC];
// CSR (built once per launch, reused by both layers)
__device__ int d_deg[N_NODES];
__device__ int d_ptr[N_NODES + 1];
__device__ int d_cursor[N_NODES];
__device__ int d_adj[ETOT];

// ---------------- GEMM: Y[N x 128] = X[N x 128] @ W[128 x 128] + b ----------
__global__ __launch_bounds__(256) void gemm128(
    const float* __restrict__ X, const float* __restrict__ W,
    const float* __restrict__ bias, float* __restrict__ Y)
{
    __shared__ float Xs[64][32];
    __shared__ float Ws[32][128];

    const int tid = threadIdx.x;
    const int tx = tid & 31;
    const int ty = tid >> 5;
    const int r0 = blockIdx.x * 64;

    float acc[8][4];
#pragma unroll
    for (int i = 0; i < 8; i++)
#pragma unroll
        for (int j = 0; j < 4; j++) acc[i][j] = 0.f;

    for (int kc = 0; kc < 128; kc += 32) {
#pragma unroll
        for (int i = 0; i < 4; i++) {
            int f = i * 256 + tid;
            int row = f >> 5, c4 = f & 31;
            *(float4*)&Ws[row][c4 * 4] =
                *(const float4*)&W[(kc + row) * 128 + c4 * 4];
        }
#pragma unroll
        for (int i = 0; i < 2; i++) {
            int f = i * 256 + tid;
            int rr = f >> 3, c4 = f & 7;
            int gr = r0 + rr;
            float4 v = make_float4(0.f, 0.f, 0.f, 0.f);
            if (gr < N_NODES)
                v = *(const float4*)&X[gr * 128 + kc + c4 * 4];
            *(float4*)&Xs[rr][c4 * 4] = v;
        }
        __syncthreads();

#pragma unroll
        for (int kk = 0; kk < 32; kk++) {
            float4 w = *(const float4*)&Ws[kk][tx * 4];
#pragma unroll
            for (int i = 0; i < 8; i++) {
                float a = Xs[ty * 8 + i][kk];
                acc[i][0] += a * w.x;
                acc[i][1] += a * w.y;
                acc[i][2] += a * w.z;
                acc[i][3] += a * w.w;
            }
        }
        __syncthreads();
    }

    float4 bv = *(const float4*)&bias[tx * 4];
#pragma unroll
    for (int i = 0; i < 8; i++) {
        int row = r0 + ty * 8 + i;
        if (row < N_NODES) {
            float4 o;
            o.x = acc[i][0] + bv.x;
            o.y = acc[i][1] + bv.y;
            o.z = acc[i][2] + bv.z;
            o.w = acc[i][3] + bv.w;
            *(float4*)&Y[row * 128 + tx * 4] = o;
        }
    }
}

// ---------------- CSR build --------------------------------------------------
__global__ void csr_deg_init()
{
    int i = blockIdx.x * blockDim.x + threadIdx.x;
    if (i < N_NODES) d_deg[i] = 1;   // self loop counted up front
}

__global__ void csr_count(const int* __restrict__ ei)
{
    int i = blockIdx.x * blockDim.x + threadIdx.x;
    if (i < E_EDGES) atomicAdd(&d_deg[ei[E_EDGES + i]], 1);
}

__global__ __launch_bounds__(1024) void csr_scan()
{
    __shared__ int part[1024];
    const int t = threadIdx.x;
    const int CH = (N_NODES + 1023) / 1024;         // 49
    int beg = t * CH;
    int end = beg + CH; if (end > N_NODES) end = N_NODES;
    if (beg > N_NODES) beg = N_NODES;

    int s = 0;
    for (int i = beg; i < end; i++) s += d_deg[i];
    part[t] = s;
    __syncthreads();
    for (int off = 1; off < 1024; off <<= 1) {
        int v = (t >= off) ? part[t - off] : 0;
        __syncthreads();
        part[t] += v;
        __syncthreads();
    }
    int run = (t == 0) ? 0 : part[t - 1];
    for (int i = beg; i < end; i++) {
        d_ptr[i] = run;
        d_cursor[i] = run;
        run += d_deg[i];
    }
    if (t == 1023) d_ptr[N_NODES] = part[1023];
}

__global__ void csr_scatter(const int* __restrict__ ei)
{
    int i = blockIdx.x * blockDim.x + threadIdx.x;
    if (i >= ETOT) return;
    int s, d;
    if (i < E_EDGES) { s = ei[i]; d = ei[E_EDGES + i]; }
    else             { s = d = i - E_EDGES; }
    int pos = atomicAdd(&d_cursor[d], 1);
    d_adj[pos] = s;
}

// ---------------- fused per-dst GATv2: scores + softmax + aggregate ---------
// one warp per dst node; no atomics anywhere.
__global__ __launch_bounds__(256) void gat_dst(
    const float* __restrict__ att, const float* __restrict__ bias)
{
    const int w = (blockIdx.x * blockDim.x + threadIdx.x) >> 5;
    const int lane = threadIdx.x & 31;
    if (w >= N_NODES) return;

    const int beg = d_ptr[w];
    const int end = d_ptr[w + 1];
    const int ch = lane * 4;
    const int h = lane >> 4;

    const float4 xr4 = *(const float4*)&d_xr[(size_t)w * HC + ch];
    const float4 av  = *(const float4*)&att[ch];

    // ---- loop 1: scores + per-head max (stored raw into d_e) ----
    float mmax = -INFINITY;
    for (int k = beg; k < end; k++) {
        int s = d_adj[k];
        float4 a = *(const float4*)&d_xl[(size_t)s * HC + ch];
        float m, p = 0.f;
        m = a.x + xr4.x; m = (m > 0.f) ? m : NEG_SLOPE * m; p += m * av.x;
        m = a.y + xr4.y; m = (m > 0.f) ? m : NEG_SLOPE * m; p += m * av.y;
        m = a.z + xr4.z; m = (m > 0.f) ? m : NEG_SLOPE * m; p += m * av.z;
        m = a.w + xr4.w; m = (m > 0.f) ? m : NEG_SLOPE * m; p += m * av.w;
        p += __shfl_down_sync(0xffffffffu, p, 8, 16);
        p += __shfl_down_sync(0xffffffffu, p, 4, 16);
        p += __shfl_down_sync(0xffffffffu, p, 2, 16);
        p += __shfl_down_sync(0xffffffffu, p, 1, 16);
        if ((lane & 15) == 0) {
            d_e[2 * k + h] = p;
            mmax = fmaxf(mmax, p);
        }
    }
    // broadcast each half's max (held at lanes 0 / 16)
    const float mh = __shfl_sync(0xffffffffu, mmax, lane & 16);

    // ---- loop 2: exp + denom (parallel over lanes within each half) ----
    float loc = 0.f;
    for (int k = beg + (lane & 15); k < end; k += 16) {
        float v = expf(d_e[2 * k + h] - mh);
        d_e[2 * k + h] = v;
        loc += v;
    }
    loc += __shfl_down_sync(0xffffffffu, loc, 8, 16);
    loc += __shfl_down_sync(0xffffffffu, loc, 4, 16);
    loc += __shfl_down_sync(0xffffffffu, loc, 2, 16);
    loc += __shfl_down_sync(0xffffffffu, loc, 1, 16);
    const float denom = __shfl_sync(0xffffffffu, loc, lane & 16);
    const float invd = 1.f / (denom + 1e-16f);

    // ---- loop 3: weighted aggregation in registers ----
    float4 acc = make_float4(0.f, 0.f, 0.f, 0.f);
    for (int k = beg; k < end; k++) {
        int s = d_adj[k];
        float alpha = d_e[2 * k + h] * invd;
        float4 a = *(const float4*)&d_xl[(size_t)s * HC + ch];
        acc.x += alpha * a.x;
        acc.y += alpha * a.y;
        acc.z += alpha * a.z;
        acc.w += alpha * a.w;
    }
    const float4 bv = *(const float4*)&bias[ch];
    float4 o;
    o.x = acc.x + bv.x; o.y = acc.y + bv.y;
    o.z = acc.z + bv.z; o.w = acc.w + bv.w;
    *(float4*)&d_acc[(size_t)w * HC + ch] = o;
}

// ---------------- GraphNorm stats: sum + sumsq in one pass ------------------
__global__ void zero_stats()
{
    int c = threadIdx.x;
    if (c < HC) { d_sum[c] = 0.f; d_sumsq[c] = 0.f; }
}

__global__ void colstats()
{
    int c = threadIdx.x;  // 128 threads
    float s = 0.f, q = 0.f;
    for (int r = blockIdx.x; r < N_NODES; r += gridDim.x) {
        float v = d_acc[r * HC + c];
        s += v;
        q += v * v;
    }
    atomicAdd(&d_sum[c], s);
    atomicAdd(&d_sumsq[c], q);
}

__global__ void norm_relu(const float* __restrict__ g,
                          const float* __restrict__ be,
                          const float* __restrict__ ms)
{
    int idx = blockIdx.x * blockDim.x + threadIdx.x;
    if (idx >= N_NODES * HC) return;
    int c = idx & 127;
    float mean = d_sum[c] * (1.f / N_NODES);
    float msq  = d_sumsq[c] * (1.f / N_NODES);
    float mm = ms[c] * mean;
    float var = msq - 2.f * mm * mean + mm * mm;   // E[(x - ms*mean)^2]
    float inv = rsqrtf(var + EPS_GN);
    float y = g[c] * (d_acc[idx] - mm) * inv + be[c];
    d_feat[idx] = (y > 0.f) ? y : 0.f;
}

// ---------------- fused MLP head: relu(feat@W1+b1)@W2+b2 --------------------
__global__ __launch_bounds__(256) void mlp_head(
    const float* __restrict__ W1, const float* __restrict__ b1,
    const float* __restrict__ W2, const float* __restrict__ b2,
    float* __restrict__ out)
{
    __shared__ float W1s[128 * 64];
    __shared__ float W2s[128];
    __shared__ float b1s[64];
    __shared__ float xs[8][128];

    int tid = threadIdx.x;
    for (int i = tid; i < 128 * 64; i += 256) W1s[i] = W1[i];
    if (tid < 128) W2s[tid] = W2[tid];
    if (tid < 64) b1s[tid] = b1[tid];
    __syncthreads();

    int w = tid >> 5, lane = tid & 31;
    float bb0 = b2[0], bb1 = b2[1];

    for (int n = blockIdx.x * 8 + w; n < N_NODES; n += gridDim.x * 8) {
        *(float4*)&xs[w][lane * 4] =
            *(const float4*)&d_feat[(size_t)n * HC + lane * 4];
        __syncwarp();

        float h0 = b1s[lane], h1 = b1s[lane + 32];
#pragma unroll
        for (int k = 0; k < 128; k++) {
            float x = xs[w][k];
            h0 += x * W1s[k * 64 + lane];
            h1 += x * W1s[k * 64 + lane + 32];
        }
        h0 = (h0 > 0.f) ? h0 : 0.f;
        h1 = (h1 > 0.f) ? h1 : 0.f;

        float p0 = h0 * W2s[lane * 2]     + h1 * W2s[(lane + 32) * 2];
        float p1 = h0 * W2s[lane * 2 + 1] + h1 * W2s[(lane + 32) * 2 + 1];
#pragma unroll
        for (int off = 16; off > 0; off >>= 1) {
            p0 += __shfl_down_sync(0xffffffffu, p0, off);
            p1 += __shfl_down_sync(0xffffffffu, p1, off);
        }
        if (lane == 0) {
            out[n * 2]     = p0 + bb0;
            out[n * 2 + 1] = p1 + bb1;
        }
        __syncwarp();
    }
}

// ---------------- driver -----------------------------------------------------
extern "C" void kernel_launch(void* const* d_in, const int* in_sizes, int n_in,
                              void* d_out, int out_size)
{
    const float* x      = (const float*)d_in[0];
    const int*   ei     = (const int*)d_in[1];
    const float* Wl0 = (const float*)d_in[2];
    const float* bl0 = (const float*)d_in[3];
    const float* Wr0 = (const float*)d_in[4];
    const float* br0 = (const float*)d_in[5];
    const float* att0  = (const float*)d_in[6];
    const float* bias0 = (const float*)d_in[7];
    const float* Wl1 = (const float*)d_in[8];
    const float* bl1 = (const float*)d_in[9];
    const float* Wr1 = (const float*)d_in[10];
    const float* br1 = (const float*)d_in[11];
    const float* att1  = (const float*)d_in[12];
    const float* bias1 = (const float*)d_in[13];
    const float* g0  = (const float*)d_in[14];
    const float* be0 = (const float*)d_in[15];
    const float* ms0 = (const float*)d_in[16];
    const float* g1  = (const float*)d_in[17];
    const float* be1 = (const float*)d_in[18];
    const float* ms1 = (const float*)d_in[19];
    const float* W1 = (const float*)d_in[20];
    const float* b1 = (const float*)d_in[21];
    const float* W2 = (const float*)d_in[22];
    const float* b2 = (const float*)d_in[23];
    float* out = (float*)d_out;

    float *p_xl, *p_xr, *p_feat;
    cudaGetSymbolAddress((void**)&p_xl,   d_xl);
    cudaGetSymbolAddress((void**)&p_xr,   d_xr);
    cudaGetSymbolAddress((void**)&p_feat, d_feat);

    const int gemm_grid = (N_NODES + 63) / 64;
    const int nrm_grid  = (N_NODES * HC + 255) / 256;
    const int gat_grid  = (N_NODES * 32 + 255) / 256;   // warp per dst

    // ---------- CSR build (once; reused by both layers) ----------
    csr_deg_init<<<(N_NODES + 255) / 256, 256>>>();
    csr_count<<<(E_EDGES + 255) / 256, 256>>>(ei);
    csr_scan<<<1, 1024>>>();
    csr_scatter<<<(ETOT + 255) / 256, 256>>>(ei);

    // ---------- layer 0 ----------
    gemm128<<<gemm_grid, 256>>>(x, Wl0, bl0, p_xl);
    gemm128<<<gemm_grid, 256>>>(x, Wr0, br0, p_xr);
    zero_stats<<<1, 128>>>();
    gat_dst<<<gat_grid, 256>>>(att0, bias0);
    colstats<<<512, 128>>>();
    norm_relu<<<nrm_grid, 256>>>(g0, be0, ms0);

    // ---------- layer 1 ----------
    gemm128<<<gemm_grid, 256>>>(p_feat, Wl1, bl1, p_xl);
    gemm128<<<gemm_grid, 256>>>(p_feat, Wr1, br1, p_xr);
    zero_stats<<<1, 128>>>();
    gat_dst<<<gat_grid, 256>>>(att1, bias1);
    colstats<<<512, 128>>>();
    norm_relu<<<nrm_grid, 256>>>(g1, be1, ms1);

    // ---------- MLP head ----------
    mlp_head<<<(N_NODES + 7) / 8, 256>>>(W1, b1, W2, b2, out);
}

// round 11
// speedup vs baseline: 1.8487x; 1.0003x over previous
#include <cuda_runtime.h>
#include <math.h>

#define N_NODES 50000
#define HC 128
#define NHEAD 2
#define CDIM 64
#define E_EDGES 800000
#define ETOT (E_EDGES + N_NODES)
#define NEG_SLOPE 0.2f
#define EPS_GN 1e-5f

typedef unsigned long long ull;

// ---------------- packed f32x2 helpers (sm_100+ FFMA2 path) ------------------
__device__ __forceinline__ ull pack2(float lo, float hi) {
    ull r;
    asm("mov.b64 %0, {%1, %2};" : "=l"(r) : "f"(lo), "f"(hi));
    return r;
}
__device__ __forceinline__ void unpack2(ull v, float& lo, float& hi) {
    asm("mov.b64 {%0, %1}, %2;" : "=f"(lo), "=f"(hi) : "l"(v));
}
__device__ __forceinline__ ull fma2(ull a, ull b, ull c) {
    ull d;
    asm("fma.rn.f32x2 %0, %1, %2, %3;" : "=l"(d) : "l"(a), "l"(b), "l"(c));
    return d;
}

// ---------------- scratch (static device globals; no allocations) ------------
__device__ float d_xl[N_NODES * HC];
__device__ float d_xr[N_NODES * HC];
__device__ float d_feat[N_NODES * HC];
__device__ float d_acc[N_NODES * HC];
__device__ float d_sum[HC];
__device__ float d_sumsq[HC];
// CSR (built once per launch, reused by both layers)
__device__ int d_deg[N_NODES];
__device__ int d_ptr[N_NODES + 1];
__device__ int d_cursor[N_NODES];
__device__ int d_adj[ETOT];

// ---------------- GEMM: Y[N x 128] = X[N x 128] @ W[128 x 128] + b ----------
// 256 threads, 64 rows/block. Inner loop uses packed fma.rn.f32x2:
// row-pairs packed in one 64-bit register (Xs stored k-major), W dup-packed.
__global__ __launch_bounds__(256) void gemm128(
    const float* __restrict__ X, const float* __restrict__ W,
    const float* __restrict__ bias, float* __restrict__ Y)
{
    __shared__ float Xs[32][66];     // [kk][row]; width 66 keeps rows 8B-aligned
    __shared__ float Ws[32][128];

    const int tid = threadIdx.x;
    const int tx = tid & 31;         // cols tx*4 .. tx*4+3
    const int ty = tid >> 5;         // rows ty*8 .. ty*8+7 (4 packed pairs)
    const int r0 = blockIdx.x * 64;

    ull acc2[4][4];                  // [row_pair][col], lo=row even, hi=row odd
#pragma unroll
    for (int i = 0; i < 4; i++)
#pragma unroll
        for (int j = 0; j < 4; j++) acc2[i][j] = 0ULL;

    for (int kc = 0; kc < 128; kc += 32) {
        // W chunk: 32x128 = 1024 float4, 4 per thread
#pragma unroll
        for (int i = 0; i < 4; i++) {
            int f = i * 256 + tid;
            int row = f >> 5, c4 = f & 31;
            *(float4*)&Ws[row][c4 * 4] =
                *(const float4*)&W[(kc + row) * 128 + c4 * 4];
        }
        // X chunk: transpose into k-major Xs[kk][row]
#pragma unroll
        for (int i = 0; i < 2; i++) {
            int f = i * 256 + tid;
            int rr = f >> 3, c4 = f & 7;
            int gr = r0 + rr;
            float4 v = make_float4(0.f, 0.f, 0.f, 0.f);
            if (gr < N_NODES)
                v = *(const float4*)&X[gr * 128 + kc + c4 * 4];
            Xs[c4 * 4 + 0][rr] = v.x;
            Xs[c4 * 4 + 1][rr] = v.y;
            Xs[c4 * 4 + 2][rr] = v.z;
            Xs[c4 * 4 + 3][rr] = v.w;
        }
        __syncthreads();

#pragma unroll 8
        for (int kk = 0; kk < 32; kk++) {
            float4 wv = *(const float4*)&Ws[kk][tx * 4];
            ull w0 = pack2(wv.x, wv.x);
            ull w1 = pack2(wv.y, wv.y);
            ull w2 = pack2(wv.z, wv.z);
            ull w3 = pack2(wv.w, wv.w);
            const ull* arow = (const ull*)&Xs[kk][ty * 8];
#pragma unroll
            for (int rp = 0; rp < 4; rp++) {
                ull a = arow[rp];
                acc2[rp][0] = fma2(a, w0, acc2[rp][0]);
                acc2[rp][1] = fma2(a, w1, acc2[rp][1]);
                acc2[rp][2] = fma2(a, w2, acc2[rp][2]);
                acc2[rp][3] = fma2(a, w3, acc2[rp][3]);
            }
        }
        __syncthreads();
    }

    float4 bv = *(const float4*)&bias[tx * 4];
#pragma unroll
    for (int rp = 0; rp < 4; rp++) {
        float lo0, hi0, lo1, hi1, lo2v, hi2v, lo3, hi3;
        unpack2(acc2[rp][0], lo0, hi0);
        unpack2(acc2[rp][1], lo1, hi1);
        unpack2(acc2[rp][2], lo2v, hi2v);
        unpack2(acc2[rp][3], lo3, hi3);
        int row = r0 + ty * 8 + rp * 2;
        if (row < N_NODES) {
            float4 o;
            o.x = lo0 + bv.x; o.y = lo1 + bv.y;
            o.z = lo2v + bv.z; o.w = lo3 + bv.w;
            *(float4*)&Y[row * 128 + tx * 4] = o;
        }
        if (row + 1 < N_NODES) {
            float4 o;
            o.x = hi0 + bv.x; o.y = hi1 + bv.y;
            o.z = hi2v + bv.z; o.w = hi3 + bv.w;
            *(float4*)&Y[(row + 1) * 128 + tx * 4] = o;
        }
    }
}

// ---------------- CSR build --------------------------------------------------
__global__ void csr_deg_init()
{
    int i = blockIdx.x * blockDim.x + threadIdx.x;
    if (i < N_NODES) d_deg[i] = 1;   // self loop counted up front
}

__global__ void csr_count(const int* __restrict__ ei)
{
    int i = blockIdx.x * blockDim.x + threadIdx.x;
    if (i < E_EDGES) atomicAdd(&d_deg[ei[E_EDGES + i]], 1);
}

__global__ __launch_bounds__(1024) void csr_scan()
{
    __shared__ int part[1024];
    const int t = threadIdx.x;
    const int CH = (N_NODES + 1023) / 1024;         // 49
    int beg = t * CH;
    int end = beg + CH; if (end > N_NODES) end = N_NODES;
    if (beg > N_NODES) beg = N_NODES;

    int s = 0;
    for (int i = beg; i < end; i++) s += d_deg[i];
    part[t] = s;
    __syncthreads();
    for (int off = 1; off < 1024; off <<= 1) {
        int v = (t >= off) ? part[t - off] : 0;
        __syncthreads();
        part[t] += v;
        __syncthreads();
    }
    int run = (t == 0) ? 0 : part[t - 1];
    for (int i = beg; i < end; i++) {
        d_ptr[i] = run;
        d_cursor[i] = run;
        run += d_deg[i];
    }
    if (t == 1023) d_ptr[N_NODES] = part[1023];
}

__global__ void csr_scatter(const int* __restrict__ ei)
{
    int i = blockIdx.x * blockDim.x + threadIdx.x;
    if (i >= ETOT) return;
    int s, d;
    if (i < E_EDGES) { s = ei[i]; d = ei[E_EDGES + i]; }
    else             { s = d = i - E_EDGES; }
    int pos = atomicAdd(&d_cursor[d], 1);
    d_adj[pos] = s;
}

// ---------------- fused per-dst GATv2: single-pass online softmax -----------
// one warp per dst node; xl gathered exactly once per edge; no atomics.
__global__ __launch_bounds__(256) void gat_dst(
    const float* __restrict__ att, const float* __restrict__ bias)
{
    const int w = (blockIdx.x * blockDim.x + threadIdx.x) >> 5;
    const int lane = threadIdx.x & 31;
    if (w >= N_NODES) return;

    const int beg = d_ptr[w];
    const int end = d_ptr[w + 1];
    const int ch = lane * 4;

    const float4 xr4 = *(const float4*)&d_xr[(size_t)w * HC + ch];
    const float4 av  = *(const float4*)&att[ch];

    float rmax = -INFINITY, rsum = 0.f;
    float4 acc = make_float4(0.f, 0.f, 0.f, 0.f);

    // prefetch stage
    int s_cur = d_adj[beg];
    float4 a_cur = *(const float4*)&d_xl[(size_t)s_cur * HC + ch];

    for (int k = beg; k < end; k++) {
        // prefetch next edge while processing current
        float4 a_nxt;
        if (k + 1 < end) {
            int s_nxt = d_adj[k + 1];
            a_nxt = *(const float4*)&d_xl[(size_t)s_nxt * HC + ch];
        }

        // score: leaky_relu(xl+xr) . att, reduced over this head's 16 lanes
        float m, p = 0.f;
        m = a_cur.x + xr4.x; m = (m > 0.f) ? m : NEG_SLOPE * m; p += m * av.x;
        m = a_cur.y + xr4.y; m = (m > 0.f) ? m : NEG_SLOPE * m; p += m * av.y;
        m = a_cur.z + xr4.z; m = (m > 0.f) ? m : NEG_SLOPE * m; p += m * av.z;
        m = a_cur.w + xr4.w; m = (m > 0.f) ? m : NEG_SLOPE * m; p += m * av.w;
        p += __shfl_xor_sync(0xffffffffu, p, 8, 16);
        p += __shfl_xor_sync(0xffffffffu, p, 4, 16);
        p += __shfl_xor_sync(0xffffffffu, p, 2, 16);
        p += __shfl_xor_sync(0xffffffffu, p, 1, 16);
        // every lane of the half now holds its head's score

        // online softmax update
        float nm   = fmaxf(rmax, p);
        float corr = expf(rmax - p > 0.f ? 0.f : rmax - nm); // == expf(rmax-nm)
        corr = expf(rmax - nm);
        float wgt  = expf(p - nm);
        rsum = rsum * corr + wgt;
        acc.x = acc.x * corr + wgt * a_cur.x;
        acc.y = acc.y * corr + wgt * a_cur.y;
        acc.z = acc.z * corr + wgt * a_cur.z;
        acc.w = acc.w * corr + wgt * a_cur.w;
        rmax = nm;

        a_cur = a_nxt;
    }

    const float invd = 1.f / (rsum + 1e-16f);
    const float4 bv = *(const float4*)&bias[ch];
    float4 o;
    o.x = acc.x * invd + bv.x;
    o.y = acc.y * invd + bv.y;
    o.z = acc.z * invd + bv.z;
    o.w = acc.w * invd + bv.w;
    *(float4*)&d_acc[(size_t)w * HC + ch] = o;
}

// ---------------- GraphNorm stats: sum + sumsq in one pass ------------------
__global__ void zero_stats()
{
    int c = threadIdx.x;
    if (c < HC) { d_sum[c] = 0.f; d_sumsq[c] = 0.f; }
}

__global__ void colstats()
{
    int c = threadIdx.x;  // 128 threads
    float s = 0.f, q = 0.f;
    for (int r = blockIdx.x; r < N_NODES; r += gridDim.x) {
        float v = d_acc[r * HC + c];
        s += v;
        q += v * v;
    }
    atomicAdd(&d_sum[c], s);
    atomicAdd(&d_sumsq[c], q);
}

__global__ void norm_relu(const float* __restrict__ g,
                          const float* __restrict__ be,
                          const float* __restrict__ ms)
{
    int idx = blockIdx.x * blockDim.x + threadIdx.x;
    if (idx >= N_NODES * HC) return;
    int c = idx & 127;
    float mean = d_sum[c] * (1.f / N_NODES);
    float msq  = d_sumsq[c] * (1.f / N_NODES);
    float mm = ms[c] * mean;
    float var = msq - 2.f * mm * mean + mm * mm;   // E[(x - ms*mean)^2]
    float inv = rsqrtf(var + EPS_GN);
    float y = g[c] * (d_acc[idx] - mm) * inv + be[c];
    d_feat[idx] = (y > 0.f) ? y : 0.f;
}

// ---------------- fused MLP head: relu(feat@W1+b1)@W2+b2 --------------------
__global__ __launch_bounds__(256) void mlp_head(
    const float* __restrict__ W1, const float* __restrict__ b1,
    const float* __restrict__ W2, const float* __restrict__ b2,
    float* __restrict__ out)
{
    __shared__ float W1s[128 * 64];
    __shared__ float W2s[128];
    __shared__ float b1s[64];
    __shared__ float xs[8][128];

    int tid = threadIdx.x;
    for (int i = tid; i < 128 * 64; i += 256) W1s[i] = W1[i];
    if (tid < 128) W2s[tid] = W2[tid];
    if (tid < 64) b1s[tid] = b1[tid];
    __syncthreads();

    int w = tid >> 5, lane = tid & 31;
    float bb0 = b2[0], bb1 = b2[1];

    for (int n = blockIdx.x * 8 + w; n < N_NODES; n += gridDim.x * 8) {
        *(float4*)&xs[w][lane * 4] =
            *(const float4*)&d_feat[(size_t)n * HC + lane * 4];
        __syncwarp();

        float h0 = b1s[lane], h1 = b1s[lane + 32];
#pragma unroll
        for (int k = 0; k < 128; k++) {
            float x = xs[w][k];
            h0 += x * W1s[k * 64 + lane];
            h1 += x * W1s[k * 64 + lane + 32];
        }
        h0 = (h0 > 0.f) ? h0 : 0.f;
        h1 = (h1 > 0.f) ? h1 : 0.f;

        float p0 = h0 * W2s[lane * 2]     + h1 * W2s[(lane + 32) * 2];
        float p1 = h0 * W2s[lane * 2 + 1] + h1 * W2s[(lane + 32) * 2 + 1];
#pragma unroll
        for (int off = 16; off > 0; off >>= 1) {
            p0 += __shfl_down_sync(0xffffffffu, p0, off);
            p1 += __shfl_down_sync(0xffffffffu, p1, off);
        }
        if (lane == 0) {
            out[n * 2]     = p0 + bb0;
            out[n * 2 + 1] = p1 + bb1;
        }
        __syncwarp();
    }
}

// ---------------- driver -----------------------------------------------------
extern "C" void kernel_launch(void* const* d_in, const int* in_sizes, int n_in,
                              void* d_out, int out_size)
{
    const float* x      = (const float*)d_in[0];
    const int*   ei     = (const int*)d_in[1];
    const float* Wl0 = (const float*)d_in[2];
    const float* bl0 = (const float*)d_in[3];
    const float* Wr0 = (const float*)d_in[4];
    const float* br0 = (const float*)d_in[5];
    const float* att0  = (const float*)d_in[6];
    const float* bias0 = (const float*)d_in[7];
    const float* Wl1 = (const float*)d_in[8];
    const float* bl1 = (const float*)d_in[9];
    const float* Wr1 = (const float*)d_in[10];
    const float* br1 = (const float*)d_in[11];
    const float* att1  = (const float*)d_in[12];
    const float* bias1 = (const float*)d_in[13];
    const float* g0  = (const float*)d_in[14];
    const float* be0 = (const float*)d_in[15];
    const float* ms0 = (const float*)d_in[16];
    const float* g1  = (const float*)d_in[17];
    const float* be1 = (const float*)d_in[18];
    const float* ms1 = (const float*)d_in[19];
    const float* W1 = (const float*)d_in[20];
    const float* b1 = (const float*)d_in[21];
    const float* W2 = (const float*)d_in[22];
    const float* b2 = (const float*)d_in[23];
    float* out = (float*)d_out;

    float *p_xl, *p_xr, *p_feat;
    cudaGetSymbolAddress((void**)&p_xl,   d_xl);
    cudaGetSymbolAddress((void**)&p_xr,   d_xr);
    cudaGetSymbolAddress((void**)&p_feat, d_feat);

    const int gemm_grid = (N_NODES + 63) / 64;
    const int nrm_grid  = (N_NODES * HC + 255) / 256;
    const int gat_grid  = (N_NODES * 32 + 255) / 256;   // warp per dst

    // ---------- CSR build (once; reused by both layers) ----------
    csr_deg_init<<<(N_NODES + 255) / 256, 256>>>();
    csr_count<<<(E_EDGES + 255) / 256, 256>>>(ei);
    csr_scan<<<1, 1024>>>();
    csr_scatter<<<(ETOT + 255) / 256, 256>>>(ei);

    // ---------- layer 0 ----------
    gemm128<<<gemm_grid, 256>>>(x, Wl0, bl0, p_xl);
    gemm128<<<gemm_grid, 256>>>(x, Wr0, br0, p_xr);
    zero_stats<<<1, 128>>>();
    gat_dst<<<gat_grid, 256>>>(att0, bias0);
    colstats<<<512, 128>>>();
    norm_relu<<<nrm_grid, 256>>>(g0, be0, ms0);

    // ---------- layer 1 ----------
    gemm128<<<gemm_grid, 256>>>(p_feat, Wl1, bl1, p_xl);
    gemm128<<<gemm_grid, 256>>>(p_feat, Wr1, br1, p_xr);
    zero_stats<<<1, 128>>>();
    gat_dst<<<gat_grid, 256>>>(att1, bias1);
    colstats<<<512, 128>>>();
    norm_relu<<<nrm_grid, 256>>>(g1, be1, ms1);

    // ---------- MLP head ----------
    mlp_head<<<(N_NODES + 7) / 8, 256>>>(W1, b1, W2, b2, out);
}

// round 12
// speedup vs baseline: 2.0684x; 1.1188x over previous
#include <cuda_runtime.h>
#include <math.h>

#define N_NODES 50000
#define HC 128
#define NHEAD 2
#define CDIM 64
#define E_EDGES 800000
#define ETOT (E_EDGES + N_NODES)
#define NEG_SLOPE 0.2f
#define EPS_GN 1e-5f

typedef unsigned long long ull;

// ---------------- packed f32x2 helpers (sm_100+ FFMA2 path) ------------------
__device__ __forceinline__ ull pack2(float lo, float hi) {
    ull r;
    asm("mov.b64 %0, {%1, %2};" : "=l"(r) : "f"(lo), "f"(hi));
    return r;
}
__device__ __forceinline__ void unpack2(ull v, float& lo, float& hi) {
    asm("mov.b64 {%0, %1}, %2;" : "=f"(lo), "=f"(hi) : "l"(v));
}
__device__ __forceinline__ ull fma2(ull a, ull b, ull c) {
    ull d;
    asm("fma.rn.f32x2 %0, %1, %2, %3;" : "=l"(d) : "l"(a), "l"(b), "l"(c));
    return d;
}

// ---------------- scratch (static device globals; no allocations) ------------
__device__ float d_xl[N_NODES * HC];
__device__ float d_xr[N_NODES * HC];
__device__ float d_feat[N_NODES * HC];
__device__ float d_acc[N_NODES * HC];
__device__ float d_sum[HC];
__device__ float d_sumsq[HC];
// CSR (built once per launch, reused by both layers)
__device__ int d_deg[N_NODES];
__device__ int d_ptr[N_NODES + 1];
__device__ int d_cursor[N_NODES];
__device__ int d_adj[ETOT];

// ------- dual GEMM: Yl = X@Wl+bl, Yr = X@Wr+br (shared X tile) ---------------
// 256 threads, 64 rows/block; FFMA2 inner loops for both outputs.
__global__ __launch_bounds__(256, 2) void gemm_dual(
    const float* __restrict__ X,
    const float* __restrict__ Wl, const float* __restrict__ bl,
    const float* __restrict__ Wr, const float* __restrict__ br,
    float* __restrict__ Yl, float* __restrict__ Yr)
{
    __shared__ float Xs[32][66];     // [kk][row]; width 66 keeps rows 8B-aligned
    __shared__ float Wls[32][128];
    __shared__ float Wrs[32][128];

    const int tid = threadIdx.x;
    const int tx = tid & 31;         // cols tx*4 .. tx*4+3
    const int ty = tid >> 5;         // rows ty*8 .. ty*8+7 (4 packed pairs)
    const int r0 = blockIdx.x * 64;

    ull accl[4][4], accr[4][4];
#pragma unroll
    for (int i = 0; i < 4; i++)
#pragma unroll
        for (int j = 0; j < 4; j++) { accl[i][j] = 0ULL; accr[i][j] = 0ULL; }

    for (int kc = 0; kc < 128; kc += 32) {
        // W chunks: 2 x (32x128) = 2048 float4 total, 8 per thread
#pragma unroll
        for (int i = 0; i < 4; i++) {
            int f = i * 256 + tid;
            int row = f >> 5, c4 = f & 31;
            *(float4*)&Wls[row][c4 * 4] =
                *(const float4*)&Wl[(kc + row) * 128 + c4 * 4];
            *(float4*)&Wrs[row][c4 * 4] =
                *(const float4*)&Wr[(kc + row) * 128 + c4 * 4];
        }
        // X chunk: transpose into k-major Xs[kk][row]
#pragma unroll
        for (int i = 0; i < 2; i++) {
            int f = i * 256 + tid;
            int rr = f >> 3, c4 = f & 7;
            int gr = r0 + rr;
            float4 v = make_float4(0.f, 0.f, 0.f, 0.f);
            if (gr < N_NODES)
                v = *(const float4*)&X[gr * 128 + kc + c4 * 4];
            Xs[c4 * 4 + 0][rr] = v.x;
            Xs[c4 * 4 + 1][rr] = v.y;
            Xs[c4 * 4 + 2][rr] = v.z;
            Xs[c4 * 4 + 3][rr] = v.w;
        }
        __syncthreads();

#pragma unroll 4
        for (int kk = 0; kk < 32; kk++) {
            const ull* arow = (const ull*)&Xs[kk][ty * 8];
            ull a0 = arow[0], a1 = arow[1], a2 = arow[2], a3 = arow[3];

            float4 wv = *(const float4*)&Wls[kk][tx * 4];
            ull w0 = pack2(wv.x, wv.x);
            ull w1 = pack2(wv.y, wv.y);
            ull w2 = pack2(wv.z, wv.z);
            ull w3 = pack2(wv.w, wv.w);
            accl[0][0] = fma2(a0, w0, accl[0][0]);
            accl[0][1] = fma2(a0, w1, accl[0][1]);
            accl[0][2] = fma2(a0, w2, accl[0][2]);
            accl[0][3] = fma2(a0, w3, accl[0][3]);
            accl[1][0] = fma2(a1, w0, accl[1][0]);
            accl[1][1] = fma2(a1, w1, accl[1][1]);
            accl[1][2] = fma2(a1, w2, accl[1][2]);
            accl[1][3] = fma2(a1, w3, accl[1][3]);
            accl[2][0] = fma2(a2, w0, accl[2][0]);
            accl[2][1] = fma2(a2, w1, accl[2][1]);
            accl[2][2] = fma2(a2, w2, accl[2][2]);
            accl[2][3] = fma2(a2, w3, accl[2][3]);
            accl[3][0] = fma2(a3, w0, accl[3][0]);
            accl[3][1] = fma2(a3, w1, accl[3][1]);
            accl[3][2] = fma2(a3, w2, accl[3][2]);
            accl[3][3] = fma2(a3, w3, accl[3][3]);

            wv = *(const float4*)&Wrs[kk][tx * 4];
            w0 = pack2(wv.x, wv.x);
            w1 = pack2(wv.y, wv.y);
            w2 = pack2(wv.z, wv.z);
            w3 = pack2(wv.w, wv.w);
            accr[0][0] = fma2(a0, w0, accr[0][0]);
            accr[0][1] = fma2(a0, w1, accr[0][1]);
            accr[0][2] = fma2(a0, w2, accr[0][2]);
            accr[0][3] = fma2(a0, w3, accr[0][3]);
            accr[1][0] = fma2(a1, w0, accr[1][0]);
            accr[1][1] = fma2(a1, w1, accr[1][1]);
            accr[1][2] = fma2(a1, w2, accr[1][2]);
            accr[1][3] = fma2(a1, w3, accr[1][3]);
            accr[2][0] = fma2(a2, w0, accr[2][0]);
            accr[2][1] = fma2(a2, w1, accr[2][1]);
            accr[2][2] = fma2(a2, w2, accr[2][2]);
            accr[2][3] = fma2(a2, w3, accr[2][3]);
            accr[3][0] = fma2(a3, w0, accr[3][0]);
            accr[3][1] = fma2(a3, w1, accr[3][1]);
            accr[3][2] = fma2(a3, w2, accr[3][2]);
            accr[3][3] = fma2(a3, w3, accr[3][3]);
        }
        __syncthreads();
    }

    float4 bvl = *(const float4*)&bl[tx * 4];
    float4 bvr = *(const float4*)&br[tx * 4];
#pragma unroll
    for (int rp = 0; rp < 4; rp++) {
        int row = r0 + ty * 8 + rp * 2;
        float e0, o0, e1, o1, e2, o2, e3, o3;
        unpack2(accl[rp][0], e0, o0);
        unpack2(accl[rp][1], e1, o1);
        unpack2(accl[rp][2], e2, o2);
        unpack2(accl[rp][3], e3, o3);
        if (row < N_NODES) {
            float4 o = make_float4(e0 + bvl.x, e1 + bvl.y, e2 + bvl.z, e3 + bvl.w);
            *(float4*)&Yl[row * 128 + tx * 4] = o;
        }
        if (row + 1 < N_NODES) {
            float4 o = make_float4(o0 + bvl.x, o1 + bvl.y, o2 + bvl.z, o3 + bvl.w);
            *(float4*)&Yl[(row + 1) * 128 + tx * 4] = o;
        }
        unpack2(accr[rp][0], e0, o0);
        unpack2(accr[rp][1], e1, o1);
        unpack2(accr[rp][2], e2, o2);
        unpack2(accr[rp][3], e3, o3);
        if (row < N_NODES) {
            float4 o = make_float4(e0 + bvr.x, e1 + bvr.y, e2 + bvr.z, e3 + bvr.w);
            *(float4*)&Yr[row * 128 + tx * 4] = o;
        }
        if (row + 1 < N_NODES) {
            float4 o = make_float4(o0 + bvr.x, o1 + bvr.y, o2 + bvr.z, o3 + bvr.w);
            *(float4*)&Yr[(row + 1) * 128 + tx * 4] = o;
        }
    }
}

// ---------------- CSR build --------------------------------------------------
__global__ void csr_deg_init()
{
    int i = blockIdx.x * blockDim.x + threadIdx.x;
    if (i < N_NODES) d_deg[i] = 1;   // self loop counted up front
}

__global__ void csr_count(const int* __restrict__ ei)
{
    int i = blockIdx.x * blockDim.x + threadIdx.x;
    if (i < E_EDGES) atomicAdd(&d_deg[ei[E_EDGES + i]], 1);
}

__global__ __launch_bounds__(1024) void csr_scan()
{
    __shared__ int part[1024];
    const int t = threadIdx.x;
    const int CH = (N_NODES + 1023) / 1024;         // 49
    int beg = t * CH;
    int end = beg + CH; if (end > N_NODES) end = N_NODES;
    if (beg > N_NODES) beg = N_NODES;

    int s = 0;
    for (int i = beg; i < end; i++) s += d_deg[i];
    part[t] = s;
    __syncthreads();
    for (int off = 1; off < 1024; off <<= 1) {
        int v = (t >= off) ? part[t - off] : 0;
        __syncthreads();
        part[t] += v;
        __syncthreads();
    }
    int run = (t == 0) ? 0 : part[t - 1];
    for (int i = beg; i < end; i++) {
        d_ptr[i] = run;
        d_cursor[i] = run;
        run += d_deg[i];
    }
    if (t == 1023) d_ptr[N_NODES] = part[1023];
}

__global__ void csr_scatter(const int* __restrict__ ei)
{
    int i = blockIdx.x * blockDim.x + threadIdx.x;
    if (i >= ETOT) return;
    int s, d;
    if (i < E_EDGES) { s = ei[i]; d = ei[E_EDGES + i]; }
    else             { s = d = i - E_EDGES; }
    int pos = atomicAdd(&d_cursor[d], 1);
    d_adj[pos] = s;
}

// ---------------- fused per-dst GATv2 (no-shift softmax, 2-way unroll) ------
// one warp per dst node; xl gathered once; iterations fully independent.
__global__ __launch_bounds__(256) void gat_dst(
    const float* __restrict__ att, const float* __restrict__ bias)
{
    const int w = (blockIdx.x * blockDim.x + threadIdx.x) >> 5;
    const int lane = threadIdx.x & 31;
    if (w >= N_NODES) return;

    const int beg = d_ptr[w];
    const int end = d_ptr[w + 1];
    const int ch = lane * 4;

    const float4 xr4 = *(const float4*)&d_xr[(size_t)w * HC + ch];
    const float4 av  = *(const float4*)&att[ch];

    float rsum = 0.f;
    float4 acc = make_float4(0.f, 0.f, 0.f, 0.f);

    int k = beg;
    for (; k + 1 < end; k += 2) {
        int s0 = d_adj[k];
        int s1 = d_adj[k + 1];
        float4 a0 = *(const float4*)&d_xl[(size_t)s0 * HC + ch];
        float4 a1 = *(const float4*)&d_xl[(size_t)s1 * HC + ch];

        float m, p0 = 0.f, p1 = 0.f;
        m = a0.x + xr4.x; m = (m > 0.f) ? m : NEG_SLOPE * m; p0 += m * av.x;
        m = a0.y + xr4.y; m = (m > 0.f) ? m : NEG_SLOPE * m; p0 += m * av.y;
        m = a0.z + xr4.z; m = (m > 0.f) ? m : NEG_SLOPE * m; p0 += m * av.z;
        m = a0.w + xr4.w; m = (m > 0.f) ? m : NEG_SLOPE * m; p0 += m * av.w;
        m = a1.x + xr4.x; m = (m > 0.f) ? m : NEG_SLOPE * m; p1 += m * av.x;
        m = a1.y + xr4.y; m = (m > 0.f) ? m : NEG_SLOPE * m; p1 += m * av.y;
        m = a1.z + xr4.z; m = (m > 0.f) ? m : NEG_SLOPE * m; p1 += m * av.z;
        m = a1.w + xr4.w; m = (m > 0.f) ? m : NEG_SLOPE * m; p1 += m * av.w;

        p0 += __shfl_xor_sync(0xffffffffu, p0, 8, 16);
        p1 += __shfl_xor_sync(0xffffffffu, p1, 8, 16);
        p0 += __shfl_xor_sync(0xffffffffu, p0, 4, 16);
        p1 += __shfl_xor_sync(0xffffffffu, p1, 4, 16);
        p0 += __shfl_xor_sync(0xffffffffu, p0, 2, 16);
        p1 += __shfl_xor_sync(0xffffffffu, p1, 2, 16);
        p0 += __shfl_xor_sync(0xffffffffu, p0, 1, 16);
        p1 += __shfl_xor_sync(0xffffffffu, p1, 1, 16);

        float w0 = __expf(p0);
        float w1 = __expf(p1);
        rsum += w0 + w1;
        acc.x += w0 * a0.x + w1 * a1.x;
        acc.y += w0 * a0.y + w1 * a1.y;
        acc.z += w0 * a0.z + w1 * a1.z;
        acc.w += w0 * a0.w + w1 * a1.w;
    }
    if (k < end) {
        int s0 = d_adj[k];
        float4 a0 = *(const float4*)&d_xl[(size_t)s0 * HC + ch];
        float m, p0 = 0.f;
        m = a0.x + xr4.x; m = (m > 0.f) ? m : NEG_SLOPE * m; p0 += m * av.x;
        m = a0.y + xr4.y; m = (m > 0.f) ? m : NEG_SLOPE * m; p0 += m * av.y;
        m = a0.z + xr4.z; m = (m > 0.f) ? m : NEG_SLOPE * m; p0 += m * av.z;
        m = a0.w + xr4.w; m = (m > 0.f) ? m : NEG_SLOPE * m; p0 += m * av.w;
        p0 += __shfl_xor_sync(0xffffffffu, p0, 8, 16);
        p0 += __shfl_xor_sync(0xffffffffu, p0, 4, 16);
        p0 += __shfl_xor_sync(0xffffffffu, p0, 2, 16);
        p0 += __shfl_xor_sync(0xffffffffu, p0, 1, 16);
        float w0 = __expf(p0);
        rsum += w0;
        acc.x += w0 * a0.x;
        acc.y += w0 * a0.y;
        acc.z += w0 * a0.z;
        acc.w += w0 * a0.w;
    }

    const float invd = 1.f / (rsum + 1e-16f);
    const float4 bv = *(const float4*)&bias[ch];
    float4 o;
    o.x = acc.x * invd + bv.x;
    o.y = acc.y * invd + bv.y;
    o.z = acc.z * invd + bv.z;
    o.w = acc.w * invd + bv.w;
    *(float4*)&d_acc[(size_t)w * HC + ch] = o;
}

// ---------------- GraphNorm stats: sum + sumsq in one pass ------------------
__global__ void zero_stats()
{
    int c = threadIdx.x;
    if (c < HC) { d_sum[c] = 0.f; d_sumsq[c] = 0.f; }
}

__global__ void colstats()
{
    int c = threadIdx.x;  // 128 threads
    float s = 0.f, q = 0.f;
    for (int r = blockIdx.x; r < N_NODES; r += gridDim.x) {
        float v = d_acc[r * HC + c];
        s += v;
        q += v * v;
    }
    atomicAdd(&d_sum[c], s);
    atomicAdd(&d_sumsq[c], q);
}

__global__ void norm_relu(const float* __restrict__ g,
                          const float* __restrict__ be,
                          const float* __restrict__ ms)
{
    int idx = blockIdx.x * blockDim.x + threadIdx.x;
    if (idx >= N_NODES * HC) return;
    int c = idx & 127;
    float mean = d_sum[c] * (1.f / N_NODES);
    float msq  = d_sumsq[c] * (1.f / N_NODES);
    float mm = ms[c] * mean;
    float var = msq - 2.f * mm * mean + mm * mm;   // E[(x - ms*mean)^2]
    float inv = rsqrtf(var + EPS_GN);
    float y = g[c] * (d_acc[idx] - mm) * inv + be[c];
    d_feat[idx] = (y > 0.f) ? y : 0.f;
}

// ---------------- fused MLP head: relu(feat@W1+b1)@W2+b2 --------------------
__global__ __launch_bounds__(256) void mlp_head(
    const float* __restrict__ W1, const float* __restrict__ b1,
    const float* __restrict__ W2, const float* __restrict__ b2,
    float* __restrict__ out)
{
    __shared__ float W1s[128 * 64];
    __shared__ float W2s[128];
    __shared__ float b1s[64];
    __shared__ float xs[8][128];

    int tid = threadIdx.x;
    for (int i = tid; i < 128 * 64; i += 256) W1s[i] = W1[i];
    if (tid < 128) W2s[tid] = W2[tid];
    if (tid < 64) b1s[tid] = b1[tid];
    __syncthreads();

    int w = tid >> 5, lane = tid & 31;
    float bb0 = b2[0], bb1 = b2[1];

    for (int n = blockIdx.x * 8 + w; n < N_NODES; n += gridDim.x * 8) {
        *(float4*)&xs[w][lane * 4] =
            *(const float4*)&d_feat[(size_t)n * HC + lane * 4];
        __syncwarp();

        float h0 = b1s[lane], h1 = b1s[lane + 32];
#pragma unroll
        for (int k = 0; k < 128; k++) {
            float x = xs[w][k];
            h0 += x * W1s[k * 64 + lane];
            h1 += x * W1s[k * 64 + lane + 32];
        }
        h0 = (h0 > 0.f) ? h0 : 0.f;
        h1 = (h1 > 0.f) ? h1 : 0.f;

        float p0 = h0 * W2s[lane * 2]     + h1 * W2s[(lane + 32) * 2];
        float p1 = h0 * W2s[lane * 2 + 1] + h1 * W2s[(lane + 32) * 2 + 1];
#pragma unroll
        for (int off = 16; off > 0; off >>= 1) {
            p0 += __shfl_down_sync(0xffffffffu, p0, off);
            p1 += __shfl_down_sync(0xffffffffu, p1, off);
        }
        if (lane == 0) {
            out[n * 2]     = p0 + bb0;
            out[n * 2 + 1] = p1 + bb1;
        }
        __syncwarp();
    }
}

// ---------------- driver -----------------------------------------------------
extern "C" void kernel_launch(void* const* d_in, const int* in_sizes, int n_in,
                              void* d_out, int out_size)
{
    const float* x      = (const float*)d_in[0];
    const int*   ei     = (const int*)d_in[1];
    const float* Wl0 = (const float*)d_in[2];
    const float* bl0 = (const float*)d_in[3];
    const float* Wr0 = (const float*)d_in[4];
    const float* br0 = (const float*)d_in[5];
    const float* att0  = (const float*)d_in[6];
    const float* bias0 = (const float*)d_in[7];
    const float* Wl1 = (const float*)d_in[8];
    const float* bl1 = (const float*)d_in[9];
    const float* Wr1 = (const float*)d_in[10];
    const float* br1 = (const float*)d_in[11];
    const float* att1  = (const float*)d_in[12];
    const float* bias1 = (const float*)d_in[13];
    const float* g0  = (const float*)d_in[14];
    const float* be0 = (const float*)d_in[15];
    const float* ms0 = (const float*)d_in[16];
    const float* g1  = (const float*)d_in[17];
    const float* be1 = (const float*)d_in[18];
    const float* ms1 = (const float*)d_in[19];
    const float* W1 = (const float*)d_in[20];
    const float* b1 = (const float*)d_in[21];
    const float* W2 = (const float*)d_in[22];
    const float* b2 = (const float*)d_in[23];
    float* out = (float*)d_out;

    float *p_xl, *p_xr, *p_feat;
    cudaGetSymbolAddress((void**)&p_xl,   d_xl);
    cudaGetSymbolAddress((void**)&p_xr,   d_xr);
    cudaGetSymbolAddress((void**)&p_feat, d_feat);

    const int gemm_grid = (N_NODES + 63) / 64;
    const int nrm_grid  = (N_NODES * HC + 255) / 256;
    const int gat_grid  = (N_NODES * 32 + 255) / 256;   // warp per dst

    // ---------- CSR build (once; reused by both layers) ----------
    csr_deg_init<<<(N_NODES + 255) / 256, 256>>>();
    csr_count<<<(E_EDGES + 255) / 256, 256>>>(ei);
    csr_scan<<<1, 1024>>>();
    csr_scatter<<<(ETOT + 255) / 256, 256>>>(ei);

    // ---------- layer 0 ----------
    gemm_dual<<<gemm_grid, 256>>>(x, Wl0, bl0, Wr0, br0, p_xl, p_xr);
    zero_stats<<<1, 128>>>();
    gat_dst<<<gat_grid, 256>>>(att0, bias0);
    colstats<<<512, 128>>>();
    norm_relu<<<nrm_grid, 256>>>(g0, be0, ms0);

    // ---------- layer 1 ----------
    gemm_dual<<<gemm_grid, 256>>>(p_feat, Wl1, bl1, Wr1, br1, p_xl, p_xr);
    zero_stats<<<1, 128>>>();
    gat_dst<<<gat_grid, 256>>>(att1, bias1);
    colstats<<<512, 128>>>();
    norm_relu<<<nrm_grid, 256>>>(g1, be1, ms1);

    // ---------- MLP head ----------
    mlp_head<<<(N_NODES + 7) / 8, 256>>>(W1, b1, W2, b2, out);
}